// round 12
// baseline (speedup 1.0000x reference)
#include <cuda_runtime.h>
#include <cstdint>

// NN_16_1_Pooling: x[16,64,224,224] f32 -> per 2x2 patch MLP (4->16 relu ->1)
// -> out[16,64,112,112] f32.
//
// R12: warps/SM is the only variable that has moved the ~54%-of-everything
// stall-coverage bound (12w: 52.5us -> 16w: 48.3us). Register diet to 5
// CTAs/SM (20 warps, cap 102 regs): hp-loop moved inside the row-pair loop
// (xp 32->16 regs, acc 8->4; weight LDS 24->48/iter but broadcast = ~1cyc),
// single-buffer weight stream (R11 double buffer was neutral), 3-buffer
// LDG.128 ring kept (80KB/SM in flight at 20 warps). Exact cover 735 blocks
// = 56(j) x 56(q) x 30(c0), chan step 30.

typedef unsigned long long u64;

#define W4 56                          // input row pitch in float4
#define IN_STEP (30 * 224 * 56)        // 30 planes, float4 units
#define OUT_STEP (30 * 112 * 56)       // 30 planes, float2 units
#define OUT_PITCH2 56                  // output row pitch in float2

__device__ __forceinline__ u64 pk2(float lo, float hi) {
    u64 r;
    asm("mov.b64 %0, {%1, %2};" : "=l"(r) : "f"(lo), "f"(hi));
    return r;
}
__device__ __forceinline__ u64 fma2(u64 a, u64 b, u64 c) {
    u64 d;
    asm("fma.rn.f32x2 %0, %1, %2, %3;" : "=l"(d) : "l"(a), "l"(b), "l"(c));
    return d;
}
__device__ __forceinline__ float2 upk(u64 v) {
    float lo, hi;
    asm("mov.b64 {%0, %1}, %2;" : "=f"(lo), "=f"(hi) : "l"(v));
    return make_float2(lo, hi);
}
__device__ __forceinline__ void lds128(u64& a, u64& b, uint32_t addr) {
    asm volatile("ld.shared.v2.b64 {%0, %1}, [%2];" : "=l"(a), "=l"(b) : "r"(addr));
}

__device__ __forceinline__ void load4(float4* v, const float4* __restrict__ p) {
    v[0] = __ldg(p);
    v[1] = __ldg(p + W4);
    v[2] = __ldg(p + 2 * W4);
    v[3] = __ldg(p + 3 * W4);
}

// One row-pair = 2 patches -> one float2.
__device__ __forceinline__ float2 row_pair(float4 tt, float4 uu,
                                           uint32_t wa, u64 bias2p) {
    // packs: xa = patch0 (t.x,t.y,u.x,u.y), xb = patch1 (t.z,t.w,u.z,u.w)
    const u64 xa0 = pk2(tt.x, tt.x), xa1 = pk2(tt.y, tt.y);
    const u64 xa2 = pk2(uu.x, uu.x), xa3 = pk2(uu.y, uu.y);
    const u64 xb0 = pk2(tt.z, tt.z), xb1 = pk2(tt.w, tt.w);
    const u64 xb2 = pk2(uu.z, uu.z), xb3 = pk2(uu.w, uu.w);

    u64 acca = bias2p, accb = bias2p;
    #pragma unroll
    for (int hp = 0; hp < 8; hp++) {
        u64 w0, w1c, w2c, w3c, bp, w2o;
        const uint32_t a = wa + hp * 64;
        lds128(w0, w1c, a);
        lds128(w2c, w3c, a + 16);
        lds128(bp, w2o, a + 32);

        u64 ha = fma2(w0, xa0, bp);
        ha = fma2(w1c, xa1, ha);
        ha = fma2(w2c, xa2, ha);
        ha = fma2(w3c, xa3, ha);
        u64 hb = fma2(w0, xb0, bp);
        hb = fma2(w1c, xb1, hb);
        hb = fma2(w2c, xb2, hb);
        hb = fma2(w3c, xb3, hb);

        const float2 hav = upk(ha);
        const float2 hbv = upk(hb);
        acca = fma2(w2o, pk2(fmaxf(hav.x, 0.0f), fmaxf(hav.y, 0.0f)), acca);
        accb = fma2(w2o, pk2(fmaxf(hbv.x, 0.0f), fmaxf(hbv.y, 0.0f)), accb);
    }
    const float2 aa = upk(acca);
    const float2 ab = upk(accb);
    return make_float2(aa.x + aa.y, ab.x + ab.y);
}

__device__ __forceinline__ void compute_store(const float4* v, uint32_t wa,
                                              u64 bias2p,
                                              float2* __restrict__ op) {
    op[0]          = row_pair(v[0], v[1], wa, bias2p);
    op[OUT_PITCH2] = row_pair(v[2], v[3], wa, bias2p);
}

__global__ __launch_bounds__(128, 5)
void mlp_pool_kernel(const float* __restrict__ x,
                     const float* __restrict__ W1,
                     const float* __restrict__ b1,
                     const float* __restrict__ W2,
                     const float* __restrict__ b2,
                     float* __restrict__ out)
{
    // s_wp[hp] = {w1p[k0..k3], b1p, w2p} padded to 64B
    __shared__ u64 s_wp[8][8];
    __shared__ float s_b2;
    if (threadIdx.x < 8) {
        const int hp = threadIdx.x;
        #pragma unroll
        for (int k = 0; k < 4; k++)
            s_wp[hp][k] = pk2(__ldg(W1 + (2 * hp) * 4 + k),
                              __ldg(W1 + (2 * hp + 1) * 4 + k));
        s_wp[hp][4] = pk2(__ldg(b1 + 2 * hp), __ldg(b1 + 2 * hp + 1));
        s_wp[hp][5] = pk2(__ldg(W2 + 2 * hp), __ldg(W2 + 2 * hp + 1));
        if (hp == 0) s_b2 = __ldg(b2);
    }
    __syncthreads();
    const u64 bias2p = pk2(s_b2, 0.0f);
    const uint32_t wa = (uint32_t)__cvta_generic_to_shared(s_wp);

    // 94080 threads = 56(j) x 56(q) x 30(c0); j,q fixed, chan += 30.
    const int tid = blockIdx.x * blockDim.x + threadIdx.x;
    const int j = tid % 56;
    const int t = tid / 56;
    const int q = t % 56;                   // output double-row
    const int c0 = t / 56;                  // 0..29
    const int n = (1023 - c0) / 30 + 1;     // 35 (c0<=3) or 34

    const float4* ip = (const float4*)x + c0 * (224 * 56) + (4 * q) * W4 + j;
    float2* op = (float2*)out + c0 * (112 * 56) + (2 * q) * OUT_PITCH2 + j;

    float4 va[4], vb[4], vc[4];

    // Prologue: stages 0,1 (n >= 34).
    load4(va, ip); ip += IN_STEP;
    load4(vb, ip); ip += IN_STEP;

    // Guard-free main: 30 iterations = 10 x 3-stage ring blocks
    // (prefetch reaches stage 31 <= n-1 = 33: always valid).
    for (int blk = 0; blk < 10; blk++) {
        load4(vc, ip); ip += IN_STEP;
        compute_store(va, wa, bias2p, op); op += OUT_STEP;
        load4(va, ip); ip += IN_STEP;
        compute_store(vb, wa, bias2p, op); op += OUT_STEP;
        load4(vb, ip); ip += IN_STEP;
        compute_store(vc, wa, bias2p, op); op += OUT_STEP;
    }

    // Tail: va=stage 30, vb=stage 31; ip -> stage 32 (always valid).
    load4(vc, ip); ip += IN_STEP;                         // 32
    compute_store(va, wa, bias2p, op); op += OUT_STEP;    // 30
    load4(va, ip); ip += IN_STEP;                         // 33 (always valid)
    compute_store(vb, wa, bias2p, op); op += OUT_STEP;    // 31
    if (n > 34) load4(vb, ip);                            // 34 (c0<=3)
    compute_store(vc, wa, bias2p, op); op += OUT_STEP;    // 32
    compute_store(va, wa, bias2p, op); op += OUT_STEP;    // 33
    if (n > 34) compute_store(vb, wa, bias2p, op);        // 34
}

extern "C" void kernel_launch(void* const* d_in, const int* in_sizes, int n_in,
                              void* d_out, int out_size)
{
    const float* x  = (const float*)d_in[0];
    const float* W1 = (const float*)d_in[1];
    const float* b1 = (const float*)d_in[2];
    const float* W2 = (const float*)d_in[3];
    const float* b2 = (const float*)d_in[4];
    float* out = (float*)d_out;

    // 735 blocks x 128 threads = 94080 = 56 * 56 * 30; 5 CTAs/SM on 147 SMs.
    mlp_pool_kernel<<<735, 128>>>(x, W1, b1, W2, b2, out);
}

// round 14
// speedup vs baseline: 1.0081x; 1.0081x over previous
#include <cuda_runtime.h>
#include <cstdint>

// NN_16_1_Pooling: x[16,64,224,224] f32 -> per 2x2 patch MLP (4->16 relu ->1)
// -> out[16,64,112,112] f32.
//
// R14 = R13 with the host-side copy bug fixed. R13 passed the __device__
// symbol g_pack as a raw src pointer (host shadow address!) -> garbage in
// c_wts -> rel_err 1.0. Now both symbols are resolved via
// cudaGetSymbolAddress (pure query, capture-safe) and the packed weights
// move device-to-device into __constant__. Kernel body unchanged:
// R10 dataflow (4 CTAs/SM, xp packs, 3-buffer LDG.128 ring, 56x56x24 exact
// cover) with weights as uniform constant-bank operands (LDCU -> UR) to cut
// FFMA2's RF-bank reciprocal throughput from 3 to 2.

typedef unsigned long long u64;

#define W4 56                          // input row pitch in float4
#define IN_STEP (24 * 224 * 56)        // 24 planes, float4 units
#define OUT_STEP (24 * 112 * 56)       // 24 planes, float2 units
#define OUT_PITCH2 56                  // output row pitch in float2

// Packed weight layout: [hp*6+0..3]=w1 k0..k3 pairs, [+4]=b1 pair, [+5]=w2
// pair, [48]={b2,0}.
__device__ u64 g_pack[49];
__constant__ u64 c_wts[49];

__device__ __forceinline__ u64 pk2(float lo, float hi) {
    u64 r;
    asm("mov.b64 %0, {%1, %2};" : "=l"(r) : "f"(lo), "f"(hi));
    return r;
}
__device__ __forceinline__ u64 fma2(u64 a, u64 b, u64 c) {
    u64 d;
    asm("fma.rn.f32x2 %0, %1, %2, %3;" : "=l"(d) : "l"(a), "l"(b), "l"(c));
    return d;
}
__device__ __forceinline__ float2 upk(u64 v) {
    float lo, hi;
    asm("mov.b64 {%0, %1}, %2;" : "=f"(lo), "=f"(hi) : "l"(v));
    return make_float2(lo, hi);
}

__global__ void pack_wts(const float* __restrict__ W1,
                         const float* __restrict__ b1,
                         const float* __restrict__ W2,
                         const float* __restrict__ b2)
{
    const int hp = threadIdx.x;
    if (hp < 8) {
        #pragma unroll
        for (int k = 0; k < 4; k++)
            g_pack[hp * 6 + k] = pk2(W1[(2 * hp) * 4 + k],
                                     W1[(2 * hp + 1) * 4 + k]);
        g_pack[hp * 6 + 4] = pk2(b1[2 * hp], b1[2 * hp + 1]);
        g_pack[hp * 6 + 5] = pk2(W2[2 * hp], W2[2 * hp + 1]);
    }
    if (hp == 0) g_pack[48] = pk2(b2[0], 0.0f);
}

__device__ __forceinline__ void load4(float4* v, const float4* __restrict__ p) {
    v[0] = __ldg(p);
    v[1] = __ldg(p + W4);
    v[2] = __ldg(p + 2 * W4);
    v[3] = __ldg(p + 3 * W4);
}

// 4 patches (2 row-pairs) per call; weights from constant memory (uniform).
__device__ __forceinline__ void compute_store(const float4* v, u64 bias2p,
                                              float2* __restrict__ op) {
    u64 xp[4][4];
    #pragma unroll
    for (int rp = 0; rp < 2; rp++) {
        const float4 tt = v[2 * rp];
        const float4 uu = v[2 * rp + 1];
        xp[2 * rp + 0][0] = pk2(tt.x, tt.x);
        xp[2 * rp + 0][1] = pk2(tt.y, tt.y);
        xp[2 * rp + 0][2] = pk2(uu.x, uu.x);
        xp[2 * rp + 0][3] = pk2(uu.y, uu.y);
        xp[2 * rp + 1][0] = pk2(tt.z, tt.z);
        xp[2 * rp + 1][1] = pk2(tt.w, tt.w);
        xp[2 * rp + 1][2] = pk2(uu.z, uu.z);
        xp[2 * rp + 1][3] = pk2(uu.w, uu.w);
    }

    u64 acc[4];
    #pragma unroll
    for (int p = 0; p < 4; p++) acc[p] = bias2p;

    #pragma unroll
    for (int hp = 0; hp < 8; hp++) {
        const u64 w0  = c_wts[hp * 6 + 0];
        const u64 w1c = c_wts[hp * 6 + 1];
        const u64 w2c = c_wts[hp * 6 + 2];
        const u64 w3c = c_wts[hp * 6 + 3];
        const u64 bp  = c_wts[hp * 6 + 4];
        const u64 w2o = c_wts[hp * 6 + 5];
        #pragma unroll
        for (int p = 0; p < 4; p++) {
            u64 h2 = fma2(w0, xp[p][0], bp);
            h2 = fma2(w1c, xp[p][1], h2);
            h2 = fma2(w2c, xp[p][2], h2);
            h2 = fma2(w3c, xp[p][3], h2);
            const float2 hv = upk(h2);
            const u64 rl = pk2(fmaxf(hv.x, 0.0f), fmaxf(hv.y, 0.0f));
            acc[p] = fma2(w2o, rl, acc[p]);
        }
    }

    const float2 a0 = upk(acc[0]);
    const float2 a1 = upk(acc[1]);
    const float2 a2 = upk(acc[2]);
    const float2 a3 = upk(acc[3]);
    op[0]          = make_float2(a0.x + a0.y, a1.x + a1.y);
    op[OUT_PITCH2] = make_float2(a2.x + a2.y, a3.x + a3.y);
}

__global__ __launch_bounds__(128, 4)
void mlp_pool_kernel(const float* __restrict__ x, float* __restrict__ out)
{
    const u64 bias2p = c_wts[48];

    // 75264 threads = 56(j) x 56(q) x 24(c0); j,q fixed, chan += 24.
    const int tid = blockIdx.x * blockDim.x + threadIdx.x;
    const int j = tid % 56;
    const int t = tid / 56;
    const int q = t % 56;                   // output double-row
    const int c0 = t / 56;                  // 0..23
    const int n = (1023 - c0) / 24 + 1;     // 43 (c0<=15) or 42

    const float4* ip = (const float4*)x + c0 * (224 * 56) + (4 * q) * W4 + j;
    float2* op = (float2*)out + c0 * (112 * 56) + (2 * q) * 56 + j;

    float4 va[4], vb[4], vc[4];

    // Prologue: stages 0,1.
    load4(va, ip); ip += IN_STEP;
    load4(vb, ip); ip += IN_STEP;

    // Guard-free main: 39 iterations = 13 x 3-stage ring blocks.
    for (int blk = 0; blk < 13; blk++) {
        load4(vc, ip); ip += IN_STEP;
        compute_store(va, bias2p, op); op += OUT_STEP;
        load4(va, ip); ip += IN_STEP;
        compute_store(vb, bias2p, op); op += OUT_STEP;
        load4(vb, ip); ip += IN_STEP;
        compute_store(vc, bias2p, op); op += OUT_STEP;
    }

    // Tail: va=stage 39, vb=stage 40; ip -> stage 41 (always valid).
    load4(vc, ip); ip += IN_STEP;                     // 41
    compute_store(va, bias2p, op); op += OUT_STEP;    // 39
    if (n > 42) load4(va, ip);                        // 42 (c0<=15)
    compute_store(vb, bias2p, op); op += OUT_STEP;    // 40
    compute_store(vc, bias2p, op); op += OUT_STEP;    // 41
    if (n > 42) compute_store(va, bias2p, op);        // 42
}

extern "C" void kernel_launch(void* const* d_in, const int* in_sizes, int n_in,
                              void* d_out, int out_size)
{
    const float* x  = (const float*)d_in[0];
    const float* W1 = (const float*)d_in[1];
    const float* b1 = (const float*)d_in[2];
    const float* W2 = (const float*)d_in[3];
    const float* b2 = (const float*)d_in[4];
    float* out = (float*)d_out;

    // 1) pack weights into __device__ scratch,
    // 2) D2D copy (REAL device address of g_pack via cudaGetSymbolAddress)
    //    into the __constant__ bank,
    // 3) main kernel. All graph-capturable.
    pack_wts<<<1, 32>>>(W1, b1, W2, b2);
    void* src = nullptr;
    cudaGetSymbolAddress(&src, g_pack);
    cudaMemcpyToSymbolAsync(c_wts, src, sizeof(u64) * 49, 0,
                            cudaMemcpyDeviceToDevice, 0);
    mlp_pool_kernel<<<588, 128>>>(x, out);
}

// round 15
// speedup vs baseline: 1.0739x; 1.0653x over previous
#include <cuda_runtime.h>
#include <cuda_fp16.h>
#include <cstdint>

// NN_16_1_Pooling: x[16,64,224,224] f32 -> per 2x2 patch MLP (4->16 relu ->1)
// -> out[16,64,112,112] f32.
//
// R15: attack the RF-bank wall itself. FFMA2 (3 x u64 operands) is rt=3 ->
// 1.5 cyc/lane; R10 is 87% saturated there. HFMA2 (3 x 32-bit operands) is
// rt=2 at 2 lanes/instr = 1 cyc/lane, and relu becomes one __hmax2. Hidden
// AND output layers run fp16 (output split across TWO fp16 accumulators to
// halve accumulation rounding), final combine + bias in fp32. Everything
// else is R10 exactly: 56x56x24 cover, 3-buffer LDG.128 ring, 4 CTAs/SM,
// in-block smem weight packing, ONE launch (R14 showed ~4us multi-launch tax).

typedef unsigned long long u64;

#define W4 56                          // input row pitch in float4
#define IN_STEP (24 * 224 * 56)        // 24 planes, float4 units
#define OUT_STEP (24 * 112 * 56)       // 24 planes, float2 units
#define OUT_PITCH2 56                  // output row pitch in float2

struct SW {
    half2 w1[8][4];   // {W1[2hp][k], W1[2hp+1][k]}
    half2 b1[8];      // {b1[2hp], b1[2hp+1]}
    half2 w2[8];      // {W2[2hp], W2[2hp+1]}
};

__device__ __forceinline__ void load4(float4* v, const float4* __restrict__ p) {
    v[0] = __ldg(p);
    v[1] = __ldg(p + W4);
    v[2] = __ldg(p + 2 * W4);
    v[3] = __ldg(p + 3 * W4);
}

// 4 patches (2 row-pairs) per call, fp16 core.
__device__ __forceinline__ void compute_store(const float4* v,
                                              const SW* __restrict__ sw,
                                              float bias2,
                                              float2* __restrict__ op) {
    // Broadcast fp16 packs: xh[p][k] = {k_val, k_val}
    half2 xh[4][4];
    #pragma unroll
    for (int rp = 0; rp < 2; rp++) {
        const float4 tt = v[2 * rp];
        const float4 uu = v[2 * rp + 1];
        xh[2 * rp + 0][0] = __float2half2_rn(tt.x);
        xh[2 * rp + 0][1] = __float2half2_rn(tt.y);
        xh[2 * rp + 0][2] = __float2half2_rn(uu.x);
        xh[2 * rp + 0][3] = __float2half2_rn(uu.y);
        xh[2 * rp + 1][0] = __float2half2_rn(tt.z);
        xh[2 * rp + 1][1] = __float2half2_rn(tt.w);
        xh[2 * rp + 1][2] = __float2half2_rn(uu.z);
        xh[2 * rp + 1][3] = __float2half2_rn(uu.w);
    }

    const half2 zero = __half2half2(__ushort_as_half(0));
    half2 accA[4], accB[4];   // split accumulation: hp 0-3 / hp 4-7
    #pragma unroll
    for (int p = 0; p < 4; p++) { accA[p] = zero; accB[p] = zero; }

    #pragma unroll
    for (int hp = 0; hp < 8; hp++) {
        const half2 w0  = sw->w1[hp][0];
        const half2 w1c = sw->w1[hp][1];
        const half2 w2c = sw->w1[hp][2];
        const half2 w3c = sw->w1[hp][3];
        const half2 bp  = sw->b1[hp];
        const half2 w2o = sw->w2[hp];
        #pragma unroll
        for (int p = 0; p < 4; p++) {
            half2 h = __hfma2(w0, xh[p][0], bp);
            h = __hfma2(w1c, xh[p][1], h);
            h = __hfma2(w2c, xh[p][2], h);
            h = __hfma2(w3c, xh[p][3], h);
            h = __hmax2(h, zero);               // packed relu, 1 instr
            if (hp < 4) accA[p] = __hfma2(w2o, h, accA[p]);
            else        accB[p] = __hfma2(w2o, h, accB[p]);
        }
    }

    float o[4];
    #pragma unroll
    for (int p = 0; p < 4; p++) {
        const float2 fa = __half22float2(accA[p]);
        const float2 fb = __half22float2(accB[p]);
        o[p] = (fa.x + fa.y) + (fb.x + fb.y) + bias2;
    }
    op[0]          = make_float2(o[0], o[1]);
    op[OUT_PITCH2] = make_float2(o[2], o[3]);
}

__global__ __launch_bounds__(128, 4)
void mlp_pool_kernel(const float* __restrict__ x,
                     const float* __restrict__ W1,
                     const float* __restrict__ b1,
                     const float* __restrict__ W2,
                     const float* __restrict__ b2,
                     float* __restrict__ out)
{
    __shared__ SW s_w;
    __shared__ float s_b2;
    if (threadIdx.x < 8) {
        const int hp = threadIdx.x;
        #pragma unroll
        for (int k = 0; k < 4; k++)
            s_w.w1[hp][k] = __floats2half2_rn(__ldg(W1 + (2 * hp) * 4 + k),
                                              __ldg(W1 + (2 * hp + 1) * 4 + k));
        s_w.b1[hp] = __floats2half2_rn(__ldg(b1 + 2 * hp), __ldg(b1 + 2 * hp + 1));
        s_w.w2[hp] = __floats2half2_rn(__ldg(W2 + 2 * hp), __ldg(W2 + 2 * hp + 1));
        if (hp == 0) s_b2 = __ldg(b2);
    }
    __syncthreads();
    const float bias2 = s_b2;

    // 75264 threads = 56(j) x 56(q) x 24(c0); j,q fixed, chan += 24.
    const int tid = blockIdx.x * blockDim.x + threadIdx.x;
    const int j = tid % 56;
    const int t = tid / 56;
    const int q = t % 56;                   // output double-row
    const int c0 = t / 56;                  // 0..23
    const int n = (1023 - c0) / 24 + 1;     // 43 (c0<=15) or 42

    const float4* ip = (const float4*)x + c0 * (224 * 56) + (4 * q) * W4 + j;
    float2* op = (float2*)out + c0 * (112 * 56) + (2 * q) * OUT_PITCH2 + j;

    float4 va[4], vb[4], vc[4];

    // Prologue: stages 0,1.
    load4(va, ip); ip += IN_STEP;
    load4(vb, ip); ip += IN_STEP;

    // Guard-free main: 39 iterations = 13 x 3-stage ring blocks.
    for (int blk = 0; blk < 13; blk++) {
        load4(vc, ip); ip += IN_STEP;
        compute_store(va, &s_w, bias2, op); op += OUT_STEP;
        load4(va, ip); ip += IN_STEP;
        compute_store(vb, &s_w, bias2, op); op += OUT_STEP;
        load4(vb, ip); ip += IN_STEP;
        compute_store(vc, &s_w, bias2, op); op += OUT_STEP;
    }

    // Tail: va=stage 39, vb=stage 40; ip -> stage 41 (always valid).
    load4(vc, ip); ip += IN_STEP;                       // 41
    compute_store(va, &s_w, bias2, op); op += OUT_STEP; // 39
    if (n > 42) load4(va, ip);                          // 42 (c0<=15)
    compute_store(vb, &s_w, bias2, op); op += OUT_STEP; // 40
    compute_store(vc, &s_w, bias2, op); op += OUT_STEP; // 41
    if (n > 42) compute_store(va, &s_w, bias2, op);     // 42
}

extern "C" void kernel_launch(void* const* d_in, const int* in_sizes, int n_in,
                              void* d_out, int out_size)
{
    const float* x  = (const float*)d_in[0];
    const float* W1 = (const float*)d_in[1];
    const float* b1 = (const float*)d_in[2];
    const float* W2 = (const float*)d_in[3];
    const float* b2 = (const float*)d_in[4];
    float* out = (float*)d_out;

    // 588 blocks x 128 threads = 75264 = 56 * 56 * 24; 4 CTAs/SM. One launch.
    mlp_pool_kernel<<<588, 128>>>(x, W1, b1, W2, b2, out);
}

// round 16
// speedup vs baseline: 1.1230x; 1.0457x over previous
#include <cuda_runtime.h>
#include <cstdint>

// NN_16_1_Pooling: x[16,64,224,224] f32 -> per 2x2 patch MLP (4->16 relu ->1)
// -> out[16,64,112,112] f32.
//
// R16: every pipe sits ~55-60% while achieved HBM BW has been pinned at
// 4.8-5.0 TB/s across totally different compute bodies (fp32 pairs, fp16,
// 12-20 warps) -> the kernel rides an achieved-bandwidth wall, not a compute
// or latency wall. Single change vs R10 (best, 48.3us kernel): STREAMING
// cache policy -- __ldcs (evict-first) on the zero-reuse input stream and
// __stcs on the output stream -- to stop 257MB of once-touched data from
// competing for L2 residency. Plus bias2 pre-packed once (-4 MOV64/iter).
// Dataflow/mapping/ring/occupancy byte-identical to R10.

typedef unsigned long long u64;

#define W4 56                          // input row pitch in float4
#define IN_STEP (24 * 224 * 56)        // 24 planes, float4 units
#define OUT_STEP (24 * 112 * 56)       // 24 planes, float2 units
#define OUT_PITCH2 56                  // output row pitch in float2

__device__ __forceinline__ u64 pk2(float lo, float hi) {
    u64 r;
    asm("mov.b64 %0, {%1, %2};" : "=l"(r) : "f"(lo), "f"(hi));
    return r;
}
__device__ __forceinline__ u64 fma2(u64 a, u64 b, u64 c) {
    u64 d;
    asm("fma.rn.f32x2 %0, %1, %2, %3;" : "=l"(d) : "l"(a), "l"(b), "l"(c));
    return d;
}
__device__ __forceinline__ float2 upk(u64 v) {
    float lo, hi;
    asm("mov.b64 {%0, %1}, %2;" : "=f"(lo), "=f"(hi) : "l"(v));
    return make_float2(lo, hi);
}

struct Wts {
    u64 w1p[8][4];   // {W1[2hp][k], W1[2hp+1][k]}
    u64 b1p[8];
    u64 w2p[8];
};

__device__ __forceinline__ void load4(float4* v, const float4* __restrict__ p) {
    v[0] = __ldcs(p);                  // evict-first: zero-reuse stream
    v[1] = __ldcs(p + W4);
    v[2] = __ldcs(p + 2 * W4);
    v[3] = __ldcs(p + 3 * W4);
}

// 4 patches (2 row-pairs) per call.
__device__ __forceinline__ void compute_store(const float4* v, const Wts& w,
                                              u64 bias2p,
                                              float2* __restrict__ op) {
    u64 xp[4][4];
    #pragma unroll
    for (int rp = 0; rp < 2; rp++) {
        const float4 tt = v[2 * rp];
        const float4 uu = v[2 * rp + 1];
        xp[2 * rp + 0][0] = pk2(tt.x, tt.x);
        xp[2 * rp + 0][1] = pk2(tt.y, tt.y);
        xp[2 * rp + 0][2] = pk2(uu.x, uu.x);
        xp[2 * rp + 0][3] = pk2(uu.y, uu.y);
        xp[2 * rp + 1][0] = pk2(tt.z, tt.z);
        xp[2 * rp + 1][1] = pk2(tt.w, tt.w);
        xp[2 * rp + 1][2] = pk2(uu.z, uu.z);
        xp[2 * rp + 1][3] = pk2(uu.w, uu.w);
    }

    u64 acc[4];
    #pragma unroll
    for (int p = 0; p < 4; p++) acc[p] = bias2p;

    #pragma unroll
    for (int hp = 0; hp < 8; hp++) {
        #pragma unroll
        for (int p = 0; p < 4; p++) {
            u64 h2 = fma2(w.w1p[hp][0], xp[p][0], w.b1p[hp]);
            h2 = fma2(w.w1p[hp][1], xp[p][1], h2);
            h2 = fma2(w.w1p[hp][2], xp[p][2], h2);
            h2 = fma2(w.w1p[hp][3], xp[p][3], h2);
            const float2 hv = upk(h2);
            const u64 rl = pk2(fmaxf(hv.x, 0.0f), fmaxf(hv.y, 0.0f));
            acc[p] = fma2(w.w2p[hp], rl, acc[p]);
        }
    }

    const float2 a0 = upk(acc[0]);
    const float2 a1 = upk(acc[1]);
    const float2 a2 = upk(acc[2]);
    const float2 a3 = upk(acc[3]);
    __stcs(op,              make_float2(a0.x + a0.y, a1.x + a1.y));
    __stcs(op + OUT_PITCH2, make_float2(a2.x + a2.y, a3.x + a3.y));
}

__global__ __launch_bounds__(128, 4)
void mlp_pool_kernel(const float* __restrict__ x,
                     const float* __restrict__ W1,
                     const float* __restrict__ b1,
                     const float* __restrict__ W2,
                     const float* __restrict__ b2,
                     float* __restrict__ out)
{
    __shared__ float s_b2;
    if (threadIdx.x == 0) s_b2 = __ldg(b2);

    Wts w;
    #pragma unroll
    for (int hp = 0; hp < 8; hp++) {
        #pragma unroll
        for (int k = 0; k < 4; k++)
            w.w1p[hp][k] = pk2(__ldg(W1 + (2 * hp) * 4 + k),
                               __ldg(W1 + (2 * hp + 1) * 4 + k));
        w.b1p[hp] = pk2(__ldg(b1 + 2 * hp), __ldg(b1 + 2 * hp + 1));
        w.w2p[hp] = pk2(__ldg(W2 + 2 * hp), __ldg(W2 + 2 * hp + 1));
    }
    __syncthreads();
    const u64 bias2p = pk2(s_b2, 0.0f);

    // 75264 threads = 56(j) x 56(q) x 24(c0); j,q fixed, chan += 24.
    const int tid = blockIdx.x * blockDim.x + threadIdx.x;
    const int j = tid % 56;
    const int t = tid / 56;
    const int q = t % 56;                   // output double-row
    const int c0 = t / 56;                  // 0..23
    const int n = (1023 - c0) / 24 + 1;     // 43 (c0<=15) or 42

    const float4* ip = (const float4*)x + c0 * (224 * 56) + (4 * q) * W4 + j;
    float2* op = (float2*)out + c0 * (112 * 56) + (2 * q) * OUT_PITCH2 + j;

    float4 va[4], vb[4], vc[4];

    // Prologue: stages 0,1.
    load4(va, ip); ip += IN_STEP;
    load4(vb, ip); ip += IN_STEP;

    // Guard-free main: 39 iterations = 13 x 3-stage ring blocks.
    for (int blk = 0; blk < 13; blk++) {
        load4(vc, ip); ip += IN_STEP;
        compute_store(va, w, bias2p, op); op += OUT_STEP;
        load4(va, ip); ip += IN_STEP;
        compute_store(vb, w, bias2p, op); op += OUT_STEP;
        load4(vb, ip); ip += IN_STEP;
        compute_store(vc, w, bias2p, op); op += OUT_STEP;
    }

    // Tail: va=stage 39, vb=stage 40; ip -> stage 41 (always valid).
    load4(vc, ip); ip += IN_STEP;                       // 41
    compute_store(va, w, bias2p, op); op += OUT_STEP;   // 39
    if (n > 42) load4(va, ip);                          // 42 (c0<=15)
    compute_store(vb, w, bias2p, op); op += OUT_STEP;   // 40
    compute_store(vc, w, bias2p, op); op += OUT_STEP;   // 41
    if (n > 42) compute_store(va, w, bias2p, op);       // 42
}

extern "C" void kernel_launch(void* const* d_in, const int* in_sizes, int n_in,
                              void* d_out, int out_size)
{
    const float* x  = (const float*)d_in[0];
    const float* W1 = (const float*)d_in[1];
    const float* b1 = (const float*)d_in[2];
    const float* W2 = (const float*)d_in[3];
    const float* b2 = (const float*)d_in[4];
    float* out = (float*)d_out;

    // 588 blocks x 128 threads = 75264 = 56 * 56 * 24; 4 CTAs/SM. One launch.
    mlp_pool_kernel<<<588, 128>>>(x, W1, b1, W2, b2, out);
}